// round 7
// baseline (speedup 1.0000x reference)
#include <cuda_runtime.h>
#include <cstdint>

// Problem constants (fixed by the dataset problem)
#define B_      256
#define D_      8192
#define S_      8
#define W_      4
#define NSLOTS_ 2048
#define SLEN_   3   // state_len = W-1

#define SLOT_BYTES    (D_ * SLEN_ * 4)           // 98304 bytes per slot
#define CHUNK_BYTES   16384
#define COPY_PARTS    (SLOT_BYTES / CHUNK_BYTES) // 6
#define CONV_BLOCKS   (B_ * D_ / 256)            // 8192 (32 blocks per batch row)
#define COPY_BLOCKS   (NSLOTS_ * COPY_PARTS)     // 12288
#define TOTAL_BLOCKS  (CONV_BLOCKS + COPY_BLOCKS) // 20480 = 4096 groups of 5
#define SMEM_BYTES    (CHUNK_BYTES + 16)         // [0:8) mbarrier, [16:+CHUNK) data

// cache_indices is int32: proven empirically in R1 — casting the buffer to
// int64* produced an illegal memory access. JAX x64-disabled downgrades
// astype(int64) -> int32.

__device__ __forceinline__ uint32_t smem_u32(const void* p) {
    uint32_t a;
    asm("{ .reg .u64 t; cvta.to.shared.u64 t, %1; cvt.u32.u64 %0, t; }" : "=r"(a) : "l"(p));
    return a;
}

// ---------------------------------------------------------------------------
// Single fused kernel with INTERLEAVED block roles.
// Launch order previously ran all conv blocks (latency-bound, ~4.4 TB/s) as
// whole waves before any copy blocks (bandwidth-bound). Remap blockIdx so
// every group of 5 consecutive blocks = 2 conv + 3 copy (exact 8192:12288
// ratio) -> every wave/SM carries both traffic types; the TMA bulk stream
// saturates DRAM while conv warps ride along.
// ---------------------------------------------------------------------------
__global__ void __launch_bounds__(256)
k_main(const float* __restrict__ x,
       const float* __restrict__ weight,
       const float* __restrict__ conv_states,
       const int* __restrict__ cache_idx,
       const int* __restrict__ res_p,
       const int* __restrict__ pad_p,
       float* __restrict__ out,
       float* __restrict__ out_states) {
    extern __shared__ char smem[];
    const int tid = threadIdx.x;

    const int group = blockIdx.x / 5;
    const int r     = blockIdx.x - group * 5;

    if (r < 2) {
        // ---- conv + residual + fresh-state write (conv_id in [0, 8192)) ----
        int cid = group * 2 + r;
        int t = cid * 256 + tid;             // 0 .. B*D-1
        int d = t & (D_ - 1);
        int b = cid >> 5;                    // 32 blocks per batch row

        int slot = cache_idx[b];
        int pad  = *pad_p;
        bool valid = (slot != pad) && (slot >= 0) && (slot < NSLOTS_);
        int safe = valid ? slot : 0;

        const float* sp = conv_states + (size_t)safe * (D_ * SLEN_) + (size_t)d * SLEN_;
        float c0 = sp[0], c1 = sp[1], c2 = sp[2];

        const float4* xp = reinterpret_cast<const float4*>(x + (size_t)t * S_);
        float4 xa = xp[0];
        float4 xb = xp[1];

        float4 wv = reinterpret_cast<const float4*>(weight)[d];

        float c[11] = {c0, c1, c2, xa.x, xa.y, xa.z, xa.w, xb.x, xb.y, xb.z, xb.w};
        float res = (*res_p != 0) ? 1.0f : 0.0f;

        float o[8];
        #pragma unroll
        for (int s = 0; s < 8; s++) {
            float acc = res * c[s + 3];
            acc = fmaf(c[s + 3], wv.w, acc);
            acc = fmaf(c[s + 2], wv.z, acc);
            acc = fmaf(c[s + 1], wv.y, acc);
            acc = fmaf(c[s + 0], wv.x, acc);
            o[s] = acc;
        }

        float4* op = reinterpret_cast<float4*>(out + (size_t)t * S_);
        op[0] = make_float4(o[0], o[1], o[2], o[3]);
        op[1] = make_float4(o[4], o[5], o[6], o[7]);

        if (valid) {
            float* np = out_states + (size_t)slot * (D_ * SLEN_) + (size_t)d * SLEN_;
            np[0] = c[8];
            np[1] = c[9];
            np[2] = c[10];
        }
    } else {
        // ---- copy untouched slots via bulk-async engine (copy_id in [0,12288)) ----
        if (tid >= 32) return;               // warp0 only
        int cb   = group * 3 + (r - 2);
        int slot = cb / COPY_PARTS;
        int part = cb - slot * COPY_PARTS;

        // Membership: 256 indices as 64 int4; each lane checks 2 int4 (8 ints).
        const int4* p4 = reinterpret_cast<const int4*>(cache_idx);
        int4 a  = p4[tid];
        int4 b4 = p4[tid + 32];
        int pad = *pad_p;
        bool hit =
            ((a.x  == slot) & (a.x  != pad)) | ((a.y  == slot) & (a.y  != pad)) |
            ((a.z  == slot) & (a.z  != pad)) | ((a.w  == slot) & (a.w  != pad)) |
            ((b4.x == slot) & (b4.x != pad)) | ((b4.y == slot) & (b4.y != pad)) |
            ((b4.z == slot) & (b4.z != pad)) | ((b4.w == slot) & (b4.w != pad));
        if (__any_sync(0xffffffffu, hit)) return;  // slot gets fresh state from conv

        if (tid == 0) {
            uint32_t sbase = smem_u32(smem);
            uint32_t mbar  = sbase;          // 8B mbarrier at offset 0
            uint32_t sdata = sbase + 16;     // 16B-aligned data region

            size_t off = (size_t)slot * SLOT_BYTES + (size_t)part * CHUNK_BYTES;
            const char* src = (const char*)conv_states + off;
            char*       dst = (char*)out_states + off;

            asm volatile("mbarrier.init.shared.b64 [%0], 1;" :: "r"(mbar) : "memory");
            asm volatile("fence.proxy.async.shared::cta;" ::: "memory");
            asm volatile("mbarrier.arrive.expect_tx.shared.b64 _, [%0], %1;"
                         :: "r"(mbar), "r"((uint32_t)CHUNK_BYTES) : "memory");
            asm volatile("cp.async.bulk.shared::cluster.global.mbarrier::complete_tx::bytes "
                         "[%0], [%1], %2, [%3];"
                         :: "r"(sdata), "l"(src), "r"((uint32_t)CHUNK_BYTES), "r"(mbar)
                         : "memory");
            // wait for the load (parity 0)
            asm volatile(
                "{\n\t"
                ".reg .pred P;\n\t"
                "WL_%=:\n\t"
                "mbarrier.try_wait.parity.shared.b64 P, [%0], 0, 0x989680;\n\t"
                "@P bra WD_%=;\n\t"
                "bra WL_%=;\n\t"
                "WD_%=:\n\t"
                "}" :: "r"(mbar) : "memory");
            // store smem -> global via bulk engine
            asm volatile("cp.async.bulk.global.shared::cta.bulk_group [%0], [%1], %2;"
                         :: "l"(dst), "r"(sdata), "r"((uint32_t)CHUNK_BYTES) : "memory");
            asm volatile("cp.async.bulk.commit_group;" ::: "memory");
            asm volatile("cp.async.bulk.wait_group 0;" ::: "memory");
        }
    }
}

// ---------------------------------------------------------------------------
// Launch — single kernel, single graph node.
// Inputs: [0]=x f32, [1]=weight f32, [2]=conv_states f32,
//         [3]=cache_indices int32, [4]=residual_connection, [5]=pad_slot_id
// Output: [out (B*D*S) | new_conv_states (NSLOTS*D*SLEN)] as f32
// ---------------------------------------------------------------------------
extern "C" void kernel_launch(void* const* d_in, const int* in_sizes, int n_in,
                              void* d_out, int out_size) {
    const float* x   = (const float*)d_in[0];
    const float* wgt = (const float*)d_in[1];
    const float* st  = (const float*)d_in[2];
    const int*   idx = (const int*)d_in[3];
    const int*   res = (const int*)d_in[4];
    const int*   pad = (const int*)d_in[5];

    float* out        = (float*)d_out;
    float* out_states = out + (size_t)B_ * D_ * S_;

    k_main<<<TOTAL_BLOCKS, 256, SMEM_BYTES>>>(x, wgt, st, idx, res, pad, out, out_states);
}